// round 10
// baseline (speedup 1.0000x reference)
#include <cuda_runtime.h>
#include <cuda_bf16.h>

#define BB 64
#define TT 512
#define DD 1024
#define F4 (DD / 4)          // 256 float4 per row
#define CQ 32                // rows per work item (chunk)
#define MAXCH (TT / CQ)      // 16 chunks per batch max
#define NTHREADS 256
#define GRID 592             // 148 SMs x 4 blocks -> uniform single wave

// Scratch (allocation-free). Partials per (b, chunk): 2 x 4 MB, L2-resident.
__device__ float4       g_ps[BB * MAXCH * F4];
__device__ float4       g_py[BB * MAXCH * F4];
__device__ unsigned int g_cnt[BB];   // zero-init; reset by epilogue each replay

// Streaming 128-bit load, evict-first policy, forced into live registers.
__device__ __forceinline__ float4 ldcs128(const float4* p) {
    float4 v;
    asm volatile("ld.global.cs.v4.f32 {%0, %1, %2, %3}, [%4];"
                 : "=f"(v.x), "=f"(v.y), "=f"(v.z), "=f"(v.w)
                 : "l"(p));
    return v;
}

__global__ __launch_bounds__(NTHREADS) void fused_kernel(
    const float* __restrict__ vseq,     // [B,T,D]
    const int*   __restrict__ slen,     // [B]
    const int*   __restrict__ words,    // [B,T]
    const float* __restrict__ weights,  // [VOCAB]
    float*       __restrict__ out)      // [2,B,D]: y then y_hat
{
    const int tid = threadIdx.x;        // = float4 column 0..255

    __shared__ int len_sh[BB];
    __shared__ int pfx[BB + 1];
    if (tid < BB) len_sh[tid] = slen[tid];
    __syncthreads();
    if (tid == 0) {
        int acc = 0;
        pfx[0] = 0;
        #pragma unroll 8
        for (int i = 0; i < BB; i++) {
            acc += (len_sh[i] + CQ - 1) / CQ;
            pfx[i + 1] = acc;
        }
    }
    __syncthreads();
    const int C = pfx[BB];              // total work items

    __shared__ float w_sh[CQ];
    __shared__ int   flag;

    for (int item = blockIdx.x; item < C; item += GRID) {
        // largest b with pfx[b] <= item (uniform across block)
        int lo = 0, hi = BB;
        while (hi - lo > 1) {
            int mid = (lo + hi) >> 1;
            if (pfx[mid] <= item) lo = mid; else hi = mid;
        }
        const int b  = lo;
        const int c  = item - pfx[b];
        const int L  = len_sh[b];
        const int t0 = c * CQ;
        const int n  = min(L - t0, CQ);   // >= 1 by construction

        __syncthreads();                  // protect w_sh reuse across items
        if (tid < n) w_sh[tid] = __ldg(&weights[words[b * TT + t0 + tid]]);
        __syncthreads();

        const float4* p = (const float4*)vseq + ((size_t)b * TT + t0) * F4 + tid;

        float4 s  = make_float4(0.f, 0.f, 0.f, 0.f);
        float4 yh = make_float4(0.f, 0.f, 0.f, 0.f);

        int t = 0;
        for (; t + 8 <= n; t += 8) {
            // 8 genuinely-in-flight LDG.128: asm volatile keeps all 8
            // results live simultaneously (forces ~32 data registers).
            float4 v[8];
            #pragma unroll
            for (int j = 0; j < 8; j++)
                v[j] = ldcs128(p + (size_t)(t + j) * F4);

            #pragma unroll
            for (int j = 0; j < 8; j++) {
                const float w = w_sh[t + j];
                s.x  += v[j].x;     s.y  += v[j].y;
                s.z  += v[j].z;     s.w  += v[j].w;
                yh.x += v[j].x * w; yh.y += v[j].y * w;
                yh.z += v[j].z * w; yh.w += v[j].w * w;
            }
        }
        for (; t < n; t++) {
            float4 v = ldcs128(p + (size_t)t * F4);
            const float w = w_sh[t];
            s.x += v.x; s.y += v.y; s.z += v.z; s.w += v.w;
            yh.x += v.x * w; yh.y += v.y * w; yh.z += v.z * w; yh.w += v.w * w;
        }

        const size_t slot = ((size_t)b * MAXCH + c) * F4 + tid;
        g_ps[slot] = s;                   // default store -> L2 write-back
        g_py[slot] = yh;

        __threadfence();                  // publish partials (release)
        if (tid == 0) {
            const int nact = pfx[b + 1] - pfx[b];
            unsigned int arrived = atomicAdd(&g_cnt[b], 1u);
            flag = (arrived == (unsigned)(nact - 1)) ? 1 : 0;
        }
        __syncthreads();

        if (flag) {
            __threadfence();              // acquire side
            const int nact = pfx[b + 1] - pfx[b];

            float4 S = make_float4(0.f, 0.f, 0.f, 0.f);
            float4 Y = make_float4(0.f, 0.f, 0.f, 0.f);
            for (int sg = 0; sg < nact; sg++) {
                const size_t sl = ((size_t)b * MAXCH + sg) * F4 + tid;
                float4 a = __ldcg(&g_ps[sl]);
                float4 h = __ldcg(&g_py[sl]);
                S.x += a.x; S.y += a.y; S.z += a.z; S.w += a.w;
                Y.x += h.x; Y.y += h.y; Y.z += h.z; Y.w += h.w;
            }

            // deterministic block-wide sum of |S| over all 1024 columns
            float a = fabsf(S.x) + fabsf(S.y) + fabsf(S.z) + fabsf(S.w);
            #pragma unroll
            for (int off = 16; off > 0; off >>= 1)
                a += __shfl_down_sync(0xffffffffu, a, off);

            __shared__ float wsum[NTHREADS / 32];
            __shared__ float rinv_sh;
            if ((tid & 31) == 0) wsum[tid >> 5] = a;
            __syncthreads();
            if (tid == 0) {
                float tot = 0.f;
                #pragma unroll
                for (int i = 0; i < NTHREADS / 32; i++) tot += wsum[i];
                rinv_sh = rsqrtf(tot);
                g_cnt[b] = 0u;            // reset for next graph replay
            }
            __syncthreads();
            const float rinv = rinv_sh;

            float4* yp  = (float4*)out + (size_t)b * F4;          // y
            float4* yhp = (float4*)out + (size_t)(BB + b) * F4;   // y_hat
            S.x *= rinv; S.y *= rinv; S.z *= rinv; S.w *= rinv;
            yp[tid]  = S;
            yhp[tid] = Y;
        }
    }
}

extern "C" void kernel_launch(void* const* d_in, const int* in_sizes, int n_in,
                              void* d_out, int out_size) {
    const float* vseq    = (const float*)d_in[0];   // [B,T,D] fp32
    const int*   slen    = (const int*)  d_in[1];   // [B] int32
    const int*   words   = (const int*)  d_in[2];   // [B,T] int32
    const float* weights = (const float*)d_in[3];   // [VOCAB] fp32
    float*       out     = (float*)d_out;           // [2*B*D] fp32: y, y_hat

    fused_kernel<<<GRID, NTHREADS>>>(vseq, slen, words, weights, out);
}

// round 11
// speedup vs baseline: 1.1633x; 1.1633x over previous
#include <cuda_runtime.h>
#include <cuda_bf16.h>

#define BB 64
#define TT 512
#define DD 1024
#define F4 (DD / 4)          // 256 float4 per row
#define CQ 16                // rows per work item (chunk)
#define MAXCH (TT / CQ)      // 32 chunks per batch max
#define NTHREADS 256
#define NBLK_SM 6
#define GRID (148 * NBLK_SM) // 888: uniform 6-block wave per SM

// Scratch (allocation-free). Partials per (b, chunk): 2 x 8 MB, L2-resident.
__device__ float4       g_ps[BB * MAXCH * F4];
__device__ float4       g_py[BB * MAXCH * F4];
__device__ unsigned int g_cnt[BB];   // zero-init; reset by epilogue each replay

__global__ __launch_bounds__(NTHREADS, NBLK_SM) void fused_kernel(
    const float* __restrict__ vseq,     // [B,T,D]
    const int*   __restrict__ slen,     // [B]
    const int*   __restrict__ words,    // [B,T]
    const float* __restrict__ weights,  // [VOCAB]
    float*       __restrict__ out)      // [2,B,D]: y then y_hat
{
    const int tid = threadIdx.x;        // = float4 column 0..255

    __shared__ int len_sh[BB];
    __shared__ int pfx[BB + 1];
    if (tid < BB) len_sh[tid] = slen[tid];
    __syncthreads();
    if (tid == 0) {
        int acc = 0;
        pfx[0] = 0;
        #pragma unroll 8
        for (int i = 0; i < BB; i++) {
            acc += (len_sh[i] + CQ - 1) / CQ;
            pfx[i + 1] = acc;
        }
    }
    __syncthreads();
    const int C = pfx[BB];              // total work items (~1056 expected)

    __shared__ float w_sh[CQ];
    __shared__ int   flag;

    for (int item = blockIdx.x; item < C; item += GRID) {
        // largest b with pfx[b] <= item (uniform across block)
        int lo = 0, hi = BB;
        while (hi - lo > 1) {
            int mid = (lo + hi) >> 1;
            if (pfx[mid] <= item) lo = mid; else hi = mid;
        }
        const int b  = lo;
        const int c  = item - pfx[b];
        const int L  = len_sh[b];
        const int t0 = c * CQ;
        const int n  = min(L - t0, CQ);   // >= 1 by construction

        __syncthreads();                  // protect w_sh reuse across items
        if (tid < n) w_sh[tid] = __ldg(&weights[words[b * TT + t0 + tid]]);
        __syncthreads();

        const float4* p = (const float4*)vseq + ((size_t)b * TT + t0) * F4 + tid;

        float4 s  = make_float4(0.f, 0.f, 0.f, 0.f);
        float4 yh = make_float4(0.f, 0.f, 0.f, 0.f);

        int t = 0;
        for (; t + 4 <= n; t += 4) {      // 4 named LDG.128 in flight
            float4 v0 = __ldcs(p + (size_t)(t + 0) * F4);
            float4 v1 = __ldcs(p + (size_t)(t + 1) * F4);
            float4 v2 = __ldcs(p + (size_t)(t + 2) * F4);
            float4 v3 = __ldcs(p + (size_t)(t + 3) * F4);
            float w0 = w_sh[t + 0], w1 = w_sh[t + 1];
            float w2 = w_sh[t + 2], w3 = w_sh[t + 3];
            s.x += v0.x; s.y += v0.y; s.z += v0.z; s.w += v0.w;
            yh.x += v0.x * w0; yh.y += v0.y * w0; yh.z += v0.z * w0; yh.w += v0.w * w0;
            s.x += v1.x; s.y += v1.y; s.z += v1.z; s.w += v1.w;
            yh.x += v1.x * w1; yh.y += v1.y * w1; yh.z += v1.z * w1; yh.w += v1.w * w1;
            s.x += v2.x; s.y += v2.y; s.z += v2.z; s.w += v2.w;
            yh.x += v2.x * w2; yh.y += v2.y * w2; yh.z += v2.z * w2; yh.w += v2.w * w2;
            s.x += v3.x; s.y += v3.y; s.z += v3.z; s.w += v3.w;
            yh.x += v3.x * w3; yh.y += v3.y * w3; yh.z += v3.z * w3; yh.w += v3.w * w3;
        }
        for (; t < n; t++) {
            float4 v = __ldcs(p + (size_t)t * F4);
            const float w = w_sh[t];
            s.x += v.x; s.y += v.y; s.z += v.z; s.w += v.w;
            yh.x += v.x * w; yh.y += v.y * w; yh.z += v.z * w; yh.w += v.w * w;
        }

        const size_t slot = ((size_t)b * MAXCH + c) * F4 + tid;
        g_ps[slot] = s;                   // default store -> L2 write-back
        g_py[slot] = yh;

        __threadfence();                  // publish partials (release)
        if (tid == 0) {
            const int nact = pfx[b + 1] - pfx[b];
            unsigned int arrived = atomicAdd(&g_cnt[b], 1u);
            flag = (arrived == (unsigned)(nact - 1)) ? 1 : 0;
        }
        __syncthreads();

        if (flag) {
            __threadfence();              // acquire side
            const int nact = pfx[b + 1] - pfx[b];

            float4 S = make_float4(0.f, 0.f, 0.f, 0.f);
            float4 Y = make_float4(0.f, 0.f, 0.f, 0.f);
            for (int sg = 0; sg < nact; sg++) {
                const size_t sl = ((size_t)b * MAXCH + sg) * F4 + tid;
                float4 a = __ldcg(&g_ps[sl]);
                float4 h = __ldcg(&g_py[sl]);
                S.x += a.x; S.y += a.y; S.z += a.z; S.w += a.w;
                Y.x += h.x; Y.y += h.y; Y.z += h.z; Y.w += h.w;
            }

            // deterministic block-wide sum of |S| over all 1024 columns
            float a = fabsf(S.x) + fabsf(S.y) + fabsf(S.z) + fabsf(S.w);
            #pragma unroll
            for (int off = 16; off > 0; off >>= 1)
                a += __shfl_down_sync(0xffffffffu, a, off);

            __shared__ float wsum[NTHREADS / 32];
            __shared__ float rinv_sh;
            if ((tid & 31) == 0) wsum[tid >> 5] = a;
            __syncthreads();
            if (tid == 0) {
                float tot = 0.f;
                #pragma unroll
                for (int i = 0; i < NTHREADS / 32; i++) tot += wsum[i];
                rinv_sh = rsqrtf(tot);
                g_cnt[b] = 0u;            // reset for next graph replay
            }
            __syncthreads();
            const float rinv = rinv_sh;

            float4* yp  = (float4*)out + (size_t)b * F4;          // y
            float4* yhp = (float4*)out + (size_t)(BB + b) * F4;   // y_hat
            S.x *= rinv; S.y *= rinv; S.z *= rinv; S.w *= rinv;
            yp[tid]  = S;
            yhp[tid] = Y;
        }
    }
}

extern "C" void kernel_launch(void* const* d_in, const int* in_sizes, int n_in,
                              void* d_out, int out_size) {
    const float* vseq    = (const float*)d_in[0];   // [B,T,D] fp32
    const int*   slen    = (const int*)  d_in[1];   // [B] int32
    const int*   words   = (const int*)  d_in[2];   // [B,T] int32
    const float* weights = (const float*)d_in[3];   // [VOCAB] fp32
    float*       out     = (float*)d_out;           // [2*B*D] fp32: y, y_hat

    fused_kernel<<<GRID, NTHREADS>>>(vseq, slen, words, weights, out);
}

// round 12
// speedup vs baseline: 1.1653x; 1.0017x over previous
#include <cuda_runtime.h>
#include <cuda_bf16.h>

#define BB 64
#define TT 512
#define DD 1024
#define F4 (DD / 4)          // 256 float4 per row
#define CQ 32                // rows per work item (chunk)
#define MAXCH (TT / CQ)      // 16 chunks per batch max
#define NTHREADS 256
#define GRID 592             // 148 SMs x 4 blocks

// Scratch (allocation-free). Partials per (b, chunk): 2 x 4 MB, L2-resident.
__device__ float4       g_ps[BB * MAXCH * F4];
__device__ float4       g_py[BB * MAXCH * F4];
__device__ unsigned int g_cnt[BB];   // zero-init; reset by epilogue each replay

__global__ __launch_bounds__(NTHREADS) void fused_kernel(
    const float* __restrict__ vseq,     // [B,T,D]
    const int*   __restrict__ slen,     // [B]
    const int*   __restrict__ words,    // [B,T]
    const float* __restrict__ weights,  // [VOCAB]
    float*       __restrict__ out)      // [2,B,D]: y then y_hat
{
    const int tid = threadIdx.x;        // = float4 column 0..255

    __shared__ int len_sh[BB];
    __shared__ int pfx[BB + 1];
    if (tid < BB) len_sh[tid] = slen[tid];
    __syncthreads();
    if (tid == 0) {
        int acc = 0;
        pfx[0] = 0;
        #pragma unroll 8
        for (int i = 0; i < BB; i++) {
            acc += (len_sh[i] + CQ - 1) / CQ;
            pfx[i + 1] = acc;
        }
    }
    __syncthreads();
    const int C = pfx[BB];              // total work items (~544 expected)

    __shared__ int flag[2];             // double-buffered by item parity
    int par = 0;

    for (int item = blockIdx.x; item < C; item += GRID, par ^= 1) {
        // largest b with pfx[b] <= item (uniform across block)
        int lo = 0, hi = BB;
        while (hi - lo > 1) {
            int mid = (lo + hi) >> 1;
            if (pfx[mid] <= item) lo = mid; else hi = mid;
        }
        const int b  = lo;
        const int c  = item - pfx[b];
        const int L  = len_sh[b];
        const int t0 = c * CQ;
        const int n  = min(L - t0, CQ);   // >= 1 by construction
        const int wbase = b * TT + t0;

        const float4* p = (const float4*)vseq + ((size_t)b * TT + t0) * F4 + tid;

        float4 s  = make_float4(0.f, 0.f, 0.f, 0.f);
        float4 yh = make_float4(0.f, 0.f, 0.f, 0.f);

        int t = 0;
        for (; t + 4 <= n; t += 4) {
            // v loads (DRAM stream) and w loads (uniform, L1/L2 broadcast)
            // are all independent -> issue together, no serial gate.
            float4 v0 = __ldcs(p + (size_t)(t + 0) * F4);
            float4 v1 = __ldcs(p + (size_t)(t + 1) * F4);
            float4 v2 = __ldcs(p + (size_t)(t + 2) * F4);
            float4 v3 = __ldcs(p + (size_t)(t + 3) * F4);
            int i0 = __ldg(&words[wbase + t + 0]);
            int i1 = __ldg(&words[wbase + t + 1]);
            int i2 = __ldg(&words[wbase + t + 2]);
            int i3 = __ldg(&words[wbase + t + 3]);
            float w0 = __ldg(&weights[i0]);
            float w1 = __ldg(&weights[i1]);
            float w2 = __ldg(&weights[i2]);
            float w3 = __ldg(&weights[i3]);
            s.x += v0.x; s.y += v0.y; s.z += v0.z; s.w += v0.w;
            yh.x += v0.x * w0; yh.y += v0.y * w0; yh.z += v0.z * w0; yh.w += v0.w * w0;
            s.x += v1.x; s.y += v1.y; s.z += v1.z; s.w += v1.w;
            yh.x += v1.x * w1; yh.y += v1.y * w1; yh.z += v1.z * w1; yh.w += v1.w * w1;
            s.x += v2.x; s.y += v2.y; s.z += v2.z; s.w += v2.w;
            yh.x += v2.x * w2; yh.y += v2.y * w2; yh.z += v2.z * w2; yh.w += v2.w * w2;
            s.x += v3.x; s.y += v3.y; s.z += v3.z; s.w += v3.w;
            yh.x += v3.x * w3; yh.y += v3.y * w3; yh.z += v3.z * w3; yh.w += v3.w * w3;
        }
        for (; t < n; t++) {
            float4 v = __ldcs(p + (size_t)t * F4);
            float  w = __ldg(&weights[__ldg(&words[wbase + t])]);
            s.x += v.x; s.y += v.y; s.z += v.z; s.w += v.w;
            yh.x += v.x * w; yh.y += v.y * w; yh.z += v.z * w; yh.w += v.w * w;
        }

        const size_t slot = ((size_t)b * MAXCH + c) * F4 + tid;
        g_ps[slot] = s;                   // default store -> L2 write-back
        g_py[slot] = yh;

        __threadfence();                  // publish partials (release)
        if (tid == 0) {
            const int nact = pfx[b + 1] - pfx[b];
            unsigned int arrived = atomicAdd(&g_cnt[b], 1u);
            flag[par] = (arrived == (unsigned)(nact - 1)) ? 1 : 0;
        }
        __syncthreads();

        if (flag[par]) {
            __threadfence();              // acquire side
            const int nact = pfx[b + 1] - pfx[b];

            float4 S = make_float4(0.f, 0.f, 0.f, 0.f);
            float4 Y = make_float4(0.f, 0.f, 0.f, 0.f);
            for (int sg = 0; sg < nact; sg++) {
                const size_t sl = ((size_t)b * MAXCH + sg) * F4 + tid;
                float4 a = __ldcg(&g_ps[sl]);
                float4 h = __ldcg(&g_py[sl]);
                S.x += a.x; S.y += a.y; S.z += a.z; S.w += a.w;
                Y.x += h.x; Y.y += h.y; Y.z += h.z; Y.w += h.w;
            }

            // deterministic block-wide sum of |S| over all 1024 columns
            float a = fabsf(S.x) + fabsf(S.y) + fabsf(S.z) + fabsf(S.w);
            #pragma unroll
            for (int off = 16; off > 0; off >>= 1)
                a += __shfl_down_sync(0xffffffffu, a, off);

            __shared__ float wsum[NTHREADS / 32];
            __shared__ float rinv_sh;
            if ((tid & 31) == 0) wsum[tid >> 5] = a;
            __syncthreads();
            if (tid == 0) {
                float tot = 0.f;
                #pragma unroll
                for (int i = 0; i < NTHREADS / 32; i++) tot += wsum[i];
                rinv_sh = rsqrtf(tot);
                g_cnt[b] = 0u;            // reset for next graph replay
            }
            __syncthreads();
            const float rinv = rinv_sh;

            float4* yp  = (float4*)out + (size_t)b * F4;          // y
            float4* yhp = (float4*)out + (size_t)(BB + b) * F4;   // y_hat
            S.x *= rinv; S.y *= rinv; S.z *= rinv; S.w *= rinv;
            yp[tid]  = S;
            yhp[tid] = Y;
        }
    }
}

extern "C" void kernel_launch(void* const* d_in, const int* in_sizes, int n_in,
                              void* d_out, int out_size) {
    const float* vseq    = (const float*)d_in[0];   // [B,T,D] fp32
    const int*   slen    = (const int*)  d_in[1];   // [B] int32
    const int*   words   = (const int*)  d_in[2];   // [B,T] int32
    const float* weights = (const float*)d_in[3];   // [VOCAB] fp32
    float*       out     = (float*)d_out;           // [2*B*D] fp32: y, y_hat

    fused_kernel<<<GRID, NTHREADS>>>(vseq, slen, words, weights, out);
}